// round 12
// baseline (speedup 1.0000x reference)
#include <cuda_runtime.h>
#include <cuda_fp16.h>
#include <cstdint>

// Problem dims (fixed)
#define BB   2
#define SS   64
#define CIN  16
#define HID  32
#define COUT 128
#define HH   64
#define WW   64
#define NN   (BB*SS)      // 128
#define HWELEMS (HH*WW)   // 4096

// scratch plane A: [n][hid][hw] packed half2(f', i'*g)   (67 MB)
// scratch plane B: [n][hid][hw] half sigmoid(o)          (33.5 MB)
__device__ uint32_t scA[(size_t)NN * HID * HWELEMS];
__device__ __half   scB[(size_t)NN * HID * HWELEMS];
// cross-CTA progress counters (persistent-grid barriers)
__device__ int g_c0;
__device__ int g_c1;

// x tile: [6 rows][66 cols][24 halves(16 ci + 8 pad)] -> uint32 words
#define XT_COL_W   12                 // words per col (24 halves)
#define XT_ROW_W   (66 * XT_COL_W)    // 792
#define XT_WORDS   (6 * XT_ROW_W)     // 4752 words = 19008 B
// weights: [64 lc][152 halves(144 k + 8 pad)] -> 76 words per lc
#define WS_LC_W    76
#define WS_WORDS   (64 * WS_LC_W)     // 4864 words = 19456 B
// dynamic smem: xt[2] | ws | bias
#define SMEM_DYN   ((2 * XT_WORDS + WS_WORDS) * 4 + 256)   // 57728

#define NCTA       296
#define B0_LIMIT   1024               // u < 1024  <=>  n < 64  <=> b = 0
#define SCAN_UNITS 65536              // per b: 32 ch x 2048 hw-pairs

__device__ __forceinline__ void mma_f16(float* d, const uint32_t* a, const uint32_t* b) {
    asm volatile(
        "mma.sync.aligned.m16n8k16.row.col.f32.f16.f16.f32 "
        "{%0,%1,%2,%3}, {%4,%5,%6,%7}, {%8,%9}, {%0,%1,%2,%3};"
        : "+f"(d[0]), "+f"(d[1]), "+f"(d[2]), "+f"(d[3])
        : "r"(a[0]), "r"(a[1]), "r"(a[2]), "r"(a[3]), "r"(b[0]), "r"(b[1]));
}
__device__ __forceinline__ void ldsm_x4(uint32_t* r, uint32_t saddr) {
    asm volatile("ldmatrix.sync.aligned.m8n8.x4.shared.b16 {%0,%1,%2,%3}, [%4];"
        : "=r"(r[0]), "=r"(r[1]), "=r"(r[2]), "=r"(r[3]) : "r"(saddr));
}
__device__ __forceinline__ uint32_t smem_u32(const void* p) {
    uint32_t a;
    asm("{ .reg .u64 t; cvta.to.shared.u64 t, %1; cvt.u32.u64 %0, t; }"
        : "=r"(a) : "l"(p));
    return a;
}
__device__ __forceinline__ uint32_t pack_h2(float lo, float hi) {
    __half2 h = __floats2half2_rn(lo, hi);
    return *reinterpret_cast<uint32_t*>(&h);
}

// Load one x-tile position (row,col) as 8 packed fp16x2 words (16 ci).
__device__ __forceinline__ void load_pos(const float* __restrict__ xn, int h0,
                                         int pidx, uint32_t* pr) {
    const int row = pidx / 66;
    const int col = pidx - row * 66;
    const int gr = h0 - 1 + row;
    const int gc = col - 1;
    if ((unsigned)gr < HH && (unsigned)gc < WW) {
        const float* src = xn + gr * WW + gc;
        #pragma unroll
        for (int j = 0; j < 8; j++)
            pr[j] = pack_h2(__ldg(src + (2 * j) * HWELEMS),
                            __ldg(src + (2 * j + 1) * HWELEMS));
    } else {
        #pragma unroll
        for (int j = 0; j < 8; j++) pr[j] = 0u;
    }
}
__device__ __forceinline__ void sts_pos(uint32_t* xtb, int pidx, const uint32_t* pr) {
    const int row = pidx / 66;
    const int col = pidx - row * 66;
    uint32_t* dst = xtb + row * XT_ROW_W + col * XT_COL_W;
    *(uint4*)(dst)     = make_uint4(pr[0], pr[1], pr[2], pr[3]);
    *(uint4*)(dst + 4) = make_uint4(pr[4], pr[5], pr[6], pr[7]);
}

// One scan sequence-pair (2 hw, all 64 timesteps) for batch b.
// __noinline__ to contain register pressure at the in-loop call site.
__device__ __noinline__ void scan_unit(int b, int unit,
                                       const float* __restrict__ c0,
                                       float* __restrict__ out,
                                       float* __restrict__ clast)
{
    const int hw = (unit & 2047) << 1;
    const int ch = unit >> 11;          // 0..31
    float2 cs = *(const float2*)&c0[((size_t)b * HID + ch) * HWELEMS + hw];
    const size_t ST = (size_t)HID * HWELEMS;
    size_t idx = ((size_t)(b * SS) * HID + ch) * HWELEMS + hw;
    const uint32_t* pA = scA + idx;
    const __half*   pB = scB + idx;
    float* op = out + idx;

    #pragma unroll 4
    for (int s = 0; s < SS; s++) {
        uint2 a = *(const uint2*)pA;
        __half2 sb = *(const __half2*)pB;
        float2 v0 = __half22float2(*reinterpret_cast<__half2*>(&a.x)); // (f', ig)
        float2 v1 = __half22float2(*reinterpret_cast<__half2*>(&a.y));
        float2 so = __half22float2(sb);
        cs.x = fmaf(v0.x, cs.x, v0.y);
        cs.y = fmaf(v1.x, cs.y, v1.y);
        *(float2*)op = make_float2(so.x * cs.x, so.y * cs.y);
        pA += ST;
        pB += ST;
        op += ST;
    }
    *(float2*)&clast[((size_t)b * HID + ch) * HWELEMS + hw] = cs;
}

// ---------------------------------------------------------------------------
// Fused persistent kernel: fp16 implicit-GEMM conv (ldmatrix feeds, software
// pipelined, in-register gate epilogue) + cross-CTA-overlapped LSTM scan.
// Grid = 296 CTAs = exactly 2/SM -> all resident -> spins are deadlock-free.
// Work order is n-major, so b=0 scratch completes halfway; scan-b0 units are
// absorbed between conv-b1 iterations (DRAM headroom under the HMMA wall);
// only the scan-b1 tail is exposed.
// ---------------------------------------------------------------------------
__global__ void __launch_bounds__(256, 2)
conv_scan_fused_kernel(const float* __restrict__ x,
                       const float* __restrict__ Wt,
                       const float* __restrict__ bias,
                       const float* __restrict__ c0,
                       float* __restrict__ out,
                       float* __restrict__ clast)
{
    extern __shared__ uint32_t smw[];
    uint32_t* xt0 = smw;
    uint32_t* xt1 = smw + XT_WORDS;
    uint32_t* ws  = smw + 2 * XT_WORDS;
    float*    bsp = (float*)(smw + 2 * XT_WORDS + WS_WORDS);

    const int tid  = threadIdx.x;
    const int lane = tid & 31;
    const int wid  = tid >> 5;
    const int gid  = lane >> 2;     // 0..7
    const int tig  = lane & 3;      // 0..3
    const int wm   = wid & 3;       // spatial row within 4-row tile
    const int wn   = wid >> 2;      // channel group (8 chans)

    const int q    = blockIdx.x & 1;   // co-half: hid chans q*16..q*16+15
    const int uid  = blockIdx.x >> 1;  // 0..147
    const int gtid = blockIdx.x * 256 + tid;

    // reset progress counters (graph replays reuse them); readers poll only
    // tens of microseconds later, all CTAs are co-resident from launch.
    if (blockIdx.x == 0 && tid == 0) {
        *(volatile int*)&g_c0 = 0;
        *(volatile int*)&g_c1 = 0;
        __threadfence();
    }

    // ---- stage weights as fp16 pairs: ws[lc][k], lc = g*16 + chan_local ----
    for (int i = tid; i < 64 * 72; i += 256) {
        int lc = i / 72, kw2 = i - lc * 72;
        int k0 = kw2 * 2;
        int cc = k0 >> 4, ci = k0 & 15;
        int co = ((lc >> 4) << 5) + (q << 4) + (lc & 15);
        float v0 = __ldg(&Wt[(co * 16 + ci)     * 9 + cc]);
        float v1 = __ldg(&Wt[(co * 16 + ci + 1) * 9 + cc]);
        ws[lc * WS_LC_W + kw2] = pack_h2(v0, v1);
    }
    if (tid < 64)
        bsp[tid] = bias[((tid >> 4) << 5) + (q << 4) + (tid & 15)];

    const int cl0 = wn * 8 + tig * 2;   // chan_local for even accum cols

    // ldmatrix per-lane address components (byte offsets)
    const int pxr   = (lane & 7) + ((lane >> 3) & 1) * 8;
    const int awoff = ((lane >> 4) & 1) * 4;
    const uint32_t aoff = (uint32_t)(pxr * XT_COL_W + awoff) * 4;
    const int bg    = (lane >> 4);
    const int bwoff = ((lane >> 3) & 1) * 4;
    const uint32_t boff = (uint32_t)(((bg << 4) + (wn << 3) + (lane & 7)) * WS_LC_W + bwoff) * 4;

    const uint32_t xt0_u = smem_u32(xt0);
    const uint32_t xt1_u = smem_u32(xt1);
    const uint32_t ws_u  = smem_u32(ws);

    // ---- prologue: load first tile into xt0 ----
    {
        const float* xn = x + (size_t)(uid >> 4) * CIN * HWELEMS;
        const int h0 = (uid & 15) << 2;
        uint32_t pr[8];
        load_pos(xn, h0, tid, pr);
        sts_pos(xt0, tid, pr);
        if (tid + 256 < 396) {
            load_pos(xn, h0, tid + 256, pr);
            sts_pos(xt0, tid + 256, pr);
        }
    }
    __syncthreads();

    bool s0done = false;
    int buf = 0;
    for (int u = uid; u < 2048; u += 148) {
        const int n  = u >> 4;
        const int h0 = (u & 15) << 2;
        const int un = u + 148;
        const bool nx = (un < 2048);

        // ---- issue next-tile loads into registers (hidden under MMA) ----
        uint32_t pr0[8], pr1[8];
        if (nx) {
            const float* xn2 = x + (size_t)(un >> 4) * CIN * HWELEMS;
            const int h02 = (un & 15) << 2;
            load_pos(xn2, h02, tid, pr0);
            if (tid + 256 < 396) load_pos(xn2, h02, tid + 256, pr1);
        }

        const uint32_t xb_u = buf ? xt1_u : xt0_u;
        uint32_t* xnb       = buf ? xt0 : xt1;

        // ---- GEMM mainloop: 9 taps, k16 per tap ----
        float acc[4][4][4];   // [mf][gate][frag]
        #pragma unroll
        for (int mf = 0; mf < 4; mf++)
            #pragma unroll
            for (int g = 0; g < 4; g++)
                #pragma unroll
                for (int e = 0; e < 4; e++) acc[mf][g][e] = 0.0f;

        #pragma unroll
        for (int cc = 0; cc < 9; cc++) {
            const int kh = cc / 3;
            const int kw = cc - kh * 3;
            uint32_t bf[4][2];
            {
                const uint32_t bbase = ws_u + boff + (uint32_t)(cc << 5);
                uint32_t r01[4], r23[4];
                ldsm_x4(r01, bbase);
                ldsm_x4(r23, bbase + 32u * WS_LC_W * 4u);
                bf[0][0] = r01[0]; bf[0][1] = r01[1];
                bf[1][0] = r01[2]; bf[1][1] = r01[3];
                bf[2][0] = r23[0]; bf[2][1] = r23[1];
                bf[3][0] = r23[2]; bf[3][1] = r23[3];
            }
            const uint32_t abase = xb_u + aoff
                + (uint32_t)((wm + kh) * XT_ROW_W + kw * XT_COL_W) * 4;
            #pragma unroll
            for (int mf = 0; mf < 4; mf++) {
                uint32_t af[4];
                ldsm_x4(af, abase + (uint32_t)(mf * 16 * XT_COL_W) * 4);
                #pragma unroll
                for (int g = 0; g < 4; g++)
                    mma_f16(acc[mf][g], af, bf[g]);
            }
        }

        // ---- store next tile to back buffer (frees pipeline regs) ----
        if (nx) {
            sts_pos(xnb, tid, pr0);
            if (tid + 256 < 396) sts_pos(xnb, tid + 256, pr1);
        }

        // ---- in-register gate epilogue -> fp16 scratch planes ----
        const int h = h0 + wm;
        const float bI0 = bsp[cl0],      bI1 = bsp[cl0 + 1];
        const float bF0 = bsp[16 + cl0], bF1 = bsp[16 + cl0 + 1];
        const float bO0 = bsp[32 + cl0], bO1 = bsp[32 + cl0 + 1];
        const float bC0 = bsp[48 + cl0], bC1 = bsp[48 + cl0 + 1];
        #pragma unroll
        for (int mf = 0; mf < 4; mf++) {
            #pragma unroll
            for (int eh = 0; eh < 2; eh++) {
                const int w = mf * 16 + gid + eh * 8;
                #pragma unroll
                for (int ec = 0; ec < 2; ec++) {
                    const int e = eh * 2 + ec;
                    float iv = acc[mf][0][e] + (ec ? bI1 : bI0);
                    float fv = acc[mf][1][e] + (ec ? bF1 : bF0);
                    float ov = acc[mf][2][e] + (ec ? bO1 : bO0);
                    float cv = acc[mf][3][e] + (ec ? bC1 : bC0);
                    float ei  = __expf(-iv);
                    float ef  = __expf(-fv);
                    float inv = __fdividef(1.f, 2.f + ei + ef);
                    float fp  = (1.f + ei) * inv;                   // f'
                    float ip  = 1.f - fp;                           // i' (exact)
                    float g   = (cv >= 0.f) ? (cv + 0.5f)
                              : __fdividef(1.f, 1.f + __expf(-cv));
                    float so  = __fdividef(1.f, 1.f + __expf(-ov));
                    const int chan = (q << 4) + cl0 + ec;
                    size_t idx = ((size_t)n * HID + chan) * HWELEMS
                                 + (size_t)h * WW + w;
                    scA[idx] = pack_h2(fp, ip * g);
                    scB[idx] = __float2half_rn(so);
                }
            }
        }

        __syncthreads();   // STS to back buffer visible before next MMA
        buf ^= 1;

        // ---- progress signaling / absorbed scan-b0 ----
        if (u < B0_LIMIT && u + 148 >= B0_LIMIT) {
            // last b=0 tile of this stripe: publish b0 scratch
            __threadfence();
            __syncthreads();
            if (tid == 0) atomicAdd(&g_c0, 1);
        } else if (u >= B0_LIMIT && !s0done) {
            if (*(volatile int*)&g_c0 >= NCTA) {   // uniform-enough; per-thread safe
                __threadfence();
                if (gtid < SCAN_UNITS) scan_unit(0, gtid, c0, out, clast);
                s0done = true;
            }
        }
    }

    // ---- publish b1 scratch ----
    __threadfence();
    __syncthreads();
    if (tid == 0) atomicAdd(&g_c1, 1);

    // ---- fallback: scan-b0 if never absorbed ----
    if (!s0done) {
        while (*(volatile int*)&g_c0 < NCTA) __nanosleep(64);
        __threadfence();
        if (gtid < SCAN_UNITS) scan_unit(0, gtid, c0, out, clast);
    }

    // ---- tail: scan-b1 ----
    while (*(volatile int*)&g_c1 < NCTA) __nanosleep(64);
    __threadfence();
    if (gtid < SCAN_UNITS) scan_unit(1, gtid, c0, out, clast);
}

// ---------------------------------------------------------------------------
extern "C" void kernel_launch(void* const* d_in, const int* in_sizes, int n_in,
                              void* d_out, int out_size)
{
    const float* x  = (const float*)d_in[0];   // (2,64,16,64,64)
    const float* Wt = (const float*)d_in[1];   // (128,16,3,3)
    const float* b  = (const float*)d_in[2];   // (128)
    const float* c0 = (const float*)d_in[3];   // (2,1,32,64,64)

    float* out   = (float*)d_out;                              // (2,64,32,64,64)
    float* clast = out + (size_t)BB * SS * HID * HWELEMS;      // (2,1,32,64,64)

    cudaFuncSetAttribute(conv_scan_fused_kernel,
                         cudaFuncAttributeMaxDynamicSharedMemorySize, SMEM_DYN);

    conv_scan_fused_kernel<<<NCTA, 256, SMEM_DYN>>>(x, Wt, b, c0, out, clast);
}

// round 13
// speedup vs baseline: 1.3179x; 1.3179x over previous
#include <cuda_runtime.h>
#include <cuda_fp16.h>
#include <cstdint>

// Problem dims (fixed)
#define BB   2
#define SS   64
#define CIN  16
#define HID  32
#define COUT 128
#define HH   64
#define WW   64
#define NN   (BB*SS)      // 128
#define HWELEMS (HH*WW)   // 4096

// scratch plane A: [n][hid][hw] packed half2(f', i'*g)   (67 MB)
// scratch plane B: [n][hid][hw] half sigmoid(o)          (33.5 MB)
__device__ uint32_t scA[(size_t)NN * HID * HWELEMS];
__device__ __half   scB[(size_t)NN * HID * HWELEMS];

// x tile: [4 rows][66 cols][24 halves(16 ci + 8 pad)] -> uint32 words
#define XT_COL_W   12                 // words per col (24 halves)
#define XT_ROW_W   (66 * XT_COL_W)    // 792
#define XT_WORDS   (4 * XT_ROW_W)     // 3168 words = 12672 B
// weights: [64 lc][152 halves(144 k + 8 pad)] -> 76 words per lc
#define WS_LC_W    76
#define WS_WORDS   (64 * WS_LC_W)     // 4864 words = 19456 B
// dynamic smem: xt[2] | ws | bias
#define SMEM_DYN   ((2 * XT_WORDS + WS_WORDS) * 4 + 256)   // 45312

#define NCTA_CONV  444                // 3 CTAs/SM x 148
#define NUNITS     8192               // (n 0..127) x (row-pair 0..31) x (q 0..1)

__device__ __forceinline__ void mma_f16(float* d, const uint32_t* a, const uint32_t* b) {
    asm volatile(
        "mma.sync.aligned.m16n8k16.row.col.f32.f16.f16.f32 "
        "{%0,%1,%2,%3}, {%4,%5,%6,%7}, {%8,%9}, {%0,%1,%2,%3};"
        : "+f"(d[0]), "+f"(d[1]), "+f"(d[2]), "+f"(d[3])
        : "r"(a[0]), "r"(a[1]), "r"(a[2]), "r"(a[3]), "r"(b[0]), "r"(b[1]));
}
__device__ __forceinline__ void ldsm_x4(uint32_t* r, uint32_t saddr) {
    asm volatile("ldmatrix.sync.aligned.m8n8.x4.shared.b16 {%0,%1,%2,%3}, [%4];"
        : "=r"(r[0]), "=r"(r[1]), "=r"(r[2]), "=r"(r[3]) : "r"(saddr));
}
__device__ __forceinline__ uint32_t smem_u32(const void* p) {
    uint32_t a;
    asm("{ .reg .u64 t; cvta.to.shared.u64 t, %1; cvt.u32.u64 %0, t; }"
        : "=r"(a) : "l"(p));
    return a;
}
__device__ __forceinline__ uint32_t pack_h2(float lo, float hi) {
    __half2 h = __floats2half2_rn(lo, hi);
    return *reinterpret_cast<uint32_t*>(&h);
}

// Load one x-tile position (row,col) as 8 packed fp16x2 words (16 ci).
// Tile rows: h0-1 .. h0+2 (2 data rows + halo).
__device__ __forceinline__ void load_pos(const float* __restrict__ xn, int h0,
                                         int pidx, uint32_t* pr) {
    const int row = pidx / 66;
    const int col = pidx - row * 66;
    const int gr = h0 - 1 + row;
    const int gc = col - 1;
    if ((unsigned)gr < HH && (unsigned)gc < WW) {
        const float* src = xn + gr * WW + gc;
        #pragma unroll
        for (int j = 0; j < 8; j++)
            pr[j] = pack_h2(__ldg(src + (2 * j) * HWELEMS),
                            __ldg(src + (2 * j + 1) * HWELEMS));
    } else {
        #pragma unroll
        for (int j = 0; j < 8; j++) pr[j] = 0u;
    }
}
__device__ __forceinline__ void sts_pos(uint32_t* xtb, int pidx, const uint32_t* pr) {
    const int row = pidx / 66;
    const int col = pidx - row * 66;
    uint32_t* dst = xtb + row * XT_ROW_W + col * XT_COL_W;
    *(uint4*)(dst)     = make_uint4(pr[0], pr[1], pr[2], pr[3]);
    *(uint4*)(dst + 4) = make_uint4(pr[4], pr[5], pr[6], pr[7]);
}

// ---------------------------------------------------------------------------
// fp16 implicit-GEMM conv, occupancy-raised: warp tile 32px x 32co
// (acc 32 regs) -> 3 CTAs/SM (24 warps) to cover the measured latency bound.
// CTA: 256 thr, tile M=128 px (2 rows x 64 w) x N=64 co (co-half q).
// Warps 4(m: row,r/w-half) x 2(n); warp N-tile = 4 gates x 8 chans ->
// gates fused in registers. ldmatrix feeds, software-pipelined x loads.
// ---------------------------------------------------------------------------
__global__ void __launch_bounds__(256, 3)
conv_gates_mma_kernel(const float* __restrict__ x,
                      const float* __restrict__ Wt,
                      const float* __restrict__ bias)
{
    extern __shared__ uint32_t smw[];
    uint32_t* xt0 = smw;
    uint32_t* xt1 = smw + XT_WORDS;
    uint32_t* ws  = smw + 2 * XT_WORDS;
    float*    bsp = (float*)(smw + 2 * XT_WORDS + WS_WORDS);

    const int tid  = threadIdx.x;
    const int lane = tid & 31;
    const int wid  = tid >> 5;
    const int gid  = lane >> 2;     // 0..7
    const int tig  = lane & 3;      // 0..3
    const int wm   = wid & 3;       // m-tile: rr = wm>>1 (row), wb = (wm&1)*32
    const int wn   = wid >> 2;      // channel group (8 chans)
    const int rr   = wm >> 1;
    const int wb   = (wm & 1) << 5;

    const int q = blockIdx.x & 1;   // co-half (NCTA_CONV even -> constant per CTA)

    // ---- stage weights as fp16 pairs: ws[lc][k], lc = g*16 + chan_local ----
    for (int i = tid; i < 64 * 72; i += 256) {
        int lc = i / 72, kw2 = i - lc * 72;
        int k0 = kw2 * 2;
        int cc = k0 >> 4, ci = k0 & 15;
        int co = ((lc >> 4) << 5) + (q << 4) + (lc & 15);
        float v0 = __ldg(&Wt[(co * 16 + ci)     * 9 + cc]);
        float v1 = __ldg(&Wt[(co * 16 + ci + 1) * 9 + cc]);
        ws[lc * WS_LC_W + kw2] = pack_h2(v0, v1);
    }
    if (tid < 64)
        bsp[tid] = bias[((tid >> 4) << 5) + (q << 4) + (tid & 15)];

    const int cl0 = wn * 8 + tig * 2;   // chan_local for even accum cols

    // ldmatrix per-lane address components (byte offsets)
    const int pxr   = (lane & 7) + ((lane >> 3) & 1) * 8;
    const int awoff = ((lane >> 4) & 1) * 4;
    const uint32_t aoff = (uint32_t)(pxr * XT_COL_W + awoff) * 4;
    const int bg    = (lane >> 4);
    const int bwoff = ((lane >> 3) & 1) * 4;
    const uint32_t boff = (uint32_t)(((bg << 4) + (wn << 3) + (lane & 7)) * WS_LC_W + bwoff) * 4;

    const uint32_t xt0_u = smem_u32(xt0);
    const uint32_t xt1_u = smem_u32(xt1);
    const uint32_t ws_u  = smem_u32(ws);

    // ---- prologue: load first tile into xt0 (264 positions, 256 threads) ----
    {
        const int v0 = blockIdx.x >> 1;           // first unit's v
        const float* xn = x + (size_t)(v0 >> 5) * CIN * HWELEMS;
        const int h0 = (v0 & 31) << 1;
        uint32_t pr[8];
        load_pos(xn, h0, tid, pr);
        sts_pos(xt0, tid, pr);
        if (tid < 8) {
            load_pos(xn, h0, tid + 256, pr);
            sts_pos(xt0, tid + 256, pr);
        }
    }
    __syncthreads();

    int buf = 0;
    for (int u = blockIdx.x; u < NUNITS; u += NCTA_CONV) {
        const int v  = u >> 1;
        const int n  = v >> 5;
        const int h0 = (v & 31) << 1;
        const int un = u + NCTA_CONV;
        const bool nx = (un < NUNITS);

        // ---- issue next-tile loads into registers (hidden under MMA) ----
        uint32_t pr0[8], pr1[8];
        if (nx) {
            const int v2 = un >> 1;
            const float* xn2 = x + (size_t)(v2 >> 5) * CIN * HWELEMS;
            const int h02 = (v2 & 31) << 1;
            load_pos(xn2, h02, tid, pr0);
            if (tid < 8) load_pos(xn2, h02, tid + 256, pr1);
        }

        const uint32_t xb_u = buf ? xt1_u : xt0_u;
        uint32_t* xnb       = buf ? xt0 : xt1;

        // ---- GEMM mainloop: 9 taps, k16 per tap ----
        float acc[2][4][4];   // [mf][gate][frag]
        #pragma unroll
        for (int mf = 0; mf < 2; mf++)
            #pragma unroll
            for (int g = 0; g < 4; g++)
                #pragma unroll
                for (int e = 0; e < 4; e++) acc[mf][g][e] = 0.0f;

        #pragma unroll
        for (int cc = 0; cc < 9; cc++) {
            const int kh = cc / 3;
            const int kw = cc - kh * 3;
            uint32_t bf[4][2];
            {
                const uint32_t bbase = ws_u + boff + (uint32_t)(cc << 5);
                uint32_t r01[4], r23[4];
                ldsm_x4(r01, bbase);
                ldsm_x4(r23, bbase + 32u * WS_LC_W * 4u);
                bf[0][0] = r01[0]; bf[0][1] = r01[1];
                bf[1][0] = r01[2]; bf[1][1] = r01[3];
                bf[2][0] = r23[0]; bf[2][1] = r23[1];
                bf[3][0] = r23[2]; bf[3][1] = r23[3];
            }
            const uint32_t abase = xb_u + aoff
                + (uint32_t)((rr + kh) * XT_ROW_W + (wb + kw) * XT_COL_W) * 4;
            #pragma unroll
            for (int mf = 0; mf < 2; mf++) {
                uint32_t af[4];
                ldsm_x4(af, abase + (uint32_t)(mf * 16 * XT_COL_W) * 4);
                #pragma unroll
                for (int g = 0; g < 4; g++)
                    mma_f16(acc[mf][g], af, bf[g]);
            }
        }

        // ---- store next tile to back buffer (frees pipeline regs) ----
        if (nx) {
            sts_pos(xnb, tid, pr0);
            if (tid < 8) sts_pos(xnb, tid + 256, pr1);
        }

        // ---- in-register gate epilogue -> fp16 scratch planes ----
        const int h = h0 + rr;
        const float bI0 = bsp[cl0],      bI1 = bsp[cl0 + 1];
        const float bF0 = bsp[16 + cl0], bF1 = bsp[16 + cl0 + 1];
        const float bO0 = bsp[32 + cl0], bO1 = bsp[32 + cl0 + 1];
        const float bC0 = bsp[48 + cl0], bC1 = bsp[48 + cl0 + 1];
        #pragma unroll
        for (int mf = 0; mf < 2; mf++) {
            #pragma unroll
            for (int eh = 0; eh < 2; eh++) {
                const int w = wb + mf * 16 + gid + eh * 8;
                #pragma unroll
                for (int ec = 0; ec < 2; ec++) {
                    const int e = eh * 2 + ec;
                    float iv = acc[mf][0][e] + (ec ? bI1 : bI0);
                    float fv = acc[mf][1][e] + (ec ? bF1 : bF0);
                    float ov = acc[mf][2][e] + (ec ? bO1 : bO0);
                    float cv = acc[mf][3][e] + (ec ? bC1 : bC0);
                    float ei  = __expf(-iv);
                    float ef  = __expf(-fv);
                    float inv = __fdividef(1.f, 2.f + ei + ef);
                    float fp  = (1.f + ei) * inv;                   // f'
                    float ip  = 1.f - fp;                           // i' (exact)
                    float g   = (cv >= 0.f) ? (cv + 0.5f)
                              : __fdividef(1.f, 1.f + __expf(-cv));
                    float so  = __fdividef(1.f, 1.f + __expf(-ov));
                    const int chan = (q << 4) + cl0 + ec;
                    size_t idx = ((size_t)n * HID + chan) * HWELEMS
                                 + (size_t)h * WW + w;
                    scA[idx] = pack_h2(fp, ip * g);
                    scB[idx] = __float2half_rn(so);
                }
            }
        }

        __syncthreads();   // STS to back buffer visible before next MMA
        buf ^= 1;
    }
}

// ---------------------------------------------------------------------------
// Scan: streaming recurrence on fp16 gate planes, 2 sequences per thread.
// At the DRAM byte wall (168 MB) — proven 26us.
// ---------------------------------------------------------------------------
__global__ void __launch_bounds__(256)
lstm_scan_kernel(const float* __restrict__ c0,
                 float* __restrict__ out,
                 float* __restrict__ clast)
{
    const int t  = blockIdx.x * blockDim.x + threadIdx.x;   // 0..131071
    const int hw = (t & 2047) << 1;
    const int ch = (t >> 11) & 31;
    const int b  = t >> 16;

    float2 cs = *(const float2*)&c0[((size_t)b * HID + ch) * HWELEMS + hw];
    const size_t ST = (size_t)HID * HWELEMS;     // per-timestep stride
    size_t idx = ((size_t)(b * SS) * HID + ch) * HWELEMS + hw;
    const uint32_t* pA = scA + idx;
    const __half*   pB = scB + idx;
    float* op = out + idx;

    #pragma unroll 4
    for (int s = 0; s < SS; s++) {
        uint2 a = *(const uint2*)pA;
        __half2 sb = *(const __half2*)pB;
        float2 v0 = __half22float2(*reinterpret_cast<__half2*>(&a.x)); // (f', ig)
        float2 v1 = __half22float2(*reinterpret_cast<__half2*>(&a.y));
        float2 so = __half22float2(sb);
        cs.x = fmaf(v0.x, cs.x, v0.y);
        cs.y = fmaf(v1.x, cs.y, v1.y);
        *(float2*)op = make_float2(so.x * cs.x, so.y * cs.y);
        pA += ST;
        pB += ST;
        op += ST;
    }
    *(float2*)&clast[((size_t)b * HID + ch) * HWELEMS + hw] = cs;
}

// ---------------------------------------------------------------------------
extern "C" void kernel_launch(void* const* d_in, const int* in_sizes, int n_in,
                              void* d_out, int out_size)
{
    const float* x  = (const float*)d_in[0];   // (2,64,16,64,64)
    const float* Wt = (const float*)d_in[1];   // (128,16,3,3)
    const float* b  = (const float*)d_in[2];   // (128)
    const float* c0 = (const float*)d_in[3];   // (2,1,32,64,64)

    float* out   = (float*)d_out;                              // (2,64,32,64,64)
    float* clast = out + (size_t)BB * SS * HID * HWELEMS;      // (2,1,32,64,64)

    cudaFuncSetAttribute(conv_gates_mma_kernel,
                         cudaFuncAttributeMaxDynamicSharedMemorySize, SMEM_DYN);

    conv_gates_mma_kernel<<<NCTA_CONV, 256, SMEM_DYN>>>(x, Wt, b);

    const int total2 = BB * HID * HWELEMS / 2;   // 131072
    lstm_scan_kernel<<<total2 / 256, 256>>>(c0, out, clast);
}